// round 16
// baseline (speedup 1.0000x reference)
#include <cuda_runtime.h>
#include <math.h>

#define NA 48
#define NS 4
#define NSHFR 16
#define NSHFA 4
#define NSHFZ 8
#define RAD_FEAT (NS * NSHFR)                     // 64
#define ANG_SUB (NSHFA * NSHFZ)                   // 32
#define NPAIRS_SP (NS * (NS + 1) / 2)             // 10
#define ANG_FEAT (NPAIRS_SP * ANG_SUB)            // 320
#define AEV_LEN (RAD_FEAT + ANG_FEAT)             // 384
#define RCR_F 5.2f
#define RCA_F 3.5f
#define PI_F 3.14159265358979323846f
#define NTHR 128
#define NWARP 4
#define CHUNK 128
#define F1STR 10
#define FULLM 0xffffffffu

__device__ __forceinline__ float pow_zeta(float x, float zeta, bool z32) {
    if (z32) {
        float y = x * x;  // ^2
        y = y * y;        // ^4
        y = y * y;        // ^8
        y = y * y;        // ^16
        return y * y;     // ^32
    }
    return __powf(x, zeta);
}

// decode triangle pair index r -> (a,b), a<b among n items
__device__ __forceinline__ void decode_tri(int r, int n, int& a, int& b) {
    float fn = (float)n;
    float tt = 2.0f * fn - 1.0f;
    a = (int)(0.5f * (tt - sqrtf(fmaxf(tt * tt - 8.0f * (float)r, 0.0f))));
    while (a > 0 && r < a * n - (a * (a + 1)) / 2) a--;
    while (r >= (a + 1) * n - ((a + 1) * (a + 2)) / 2) a++;
    b = r - (a * n - (a * (a + 1)) / 2) + a + 1;
}

__global__ __launch_bounds__(NTHR, 12)
void aev_kernel(const float* __restrict__ coords,   // (M, A, 3)
                const float* __restrict__ gEtaR,
                const float* __restrict__ gShfR,    // (16,)
                const float* __restrict__ gEtaA,
                const float* __restrict__ gZeta,
                const float* __restrict__ gShfA,    // (4,)
                const float* __restrict__ gShfZ,    // (8,)
                const int*   __restrict__ species,  // (M, A)
                float* __restrict__ out)            // (M, A, 384)
{
    const int i = blockIdx.x;
    const int m = blockIdx.y;
    const int tid = threadIdx.x;
    const int lane = tid & 31;
    const int wid = tid >> 5;
    const unsigned ltm = (1u << lane) - 1u;

    __shared__ float scrd[NA * 3];                 // flat xyz
    __shared__ int   ssp[NA];
    __shared__ float shfr[NSHFR], shfa[NSHFA];
    __shared__ float cshfz[NSHFZ], sshfz[NSHFZ];
    __shared__ float s_etaR, s_etaA, s_zeta;
    __shared__ float dR[NA], qfcR[NA];             // radial list, species-sorted
    __shared__ int   cntRspw[NWARP][NS];
    __shared__ int   cntAspw[NWARP][NS];
    __shared__ int   rstart[NS + 1];
    __shared__ int   astart[NS + 1];               // angular species-segment starts
    __shared__ int   pbnd[NPAIRS_SP + 1];          // bucket pair-index bounds
    // angular list, species-sorted
    __shared__ float avx[NA], avy[NA], avz[NA], ad[NA], afc[NA], arinv[NA];
    __shared__ float f1s[CHUNK * F1STR];
    __shared__ float f2s[CHUNK * 5];

    // ---- phase 0: load (spread across warps) ----
    if (tid < 36)
        ((float4*)scrd)[tid] = ((const float4*)(coords + (size_t)m * NA * 3))[tid];
    if (tid >= 64 && tid < 64 + NA)
        ssp[tid - 64] = species[(size_t)m * NA + (tid - 64)];
    if (tid >= 36 && tid < 52) shfr[tid - 36] = gShfR[tid - 36];
    if (tid >= 52 && tid < 56) shfa[tid - 52] = gShfA[tid - 52];
    if (tid >= 112 && tid < 120) {
        float z = gShfZ[tid - 112];
        cshfz[tid - 112] = cosf(z);
        sshfz[tid - 112] = sinf(z);
    }
    if (tid == 120) s_etaR = gEtaR[0];
    if (tid == 121) s_etaA = gEtaA[0];
    if (tid == 122) s_zeta = gZeta[0];
    __syncthreads();

    const float cx = scrd[i * 3], cy = scrd[i * 3 + 1], cz = scrd[i * 3 + 2];
    const float etaR = s_etaR, etaA = s_etaA, zeta = s_zeta;
    const bool z32 = (zeta == 32.0f);

    // ---- phase 1: compaction; BOTH lists species-sorted ----
    {
        int j = tid;
        bool valid = (j < NA) && (j != i);
        float dx = 0.f, dy = 0.f, dz = 0.f, d = 1e9f;
        int sp = 0;
        if (valid) {
            dx = scrd[j * 3] - cx;
            dy = scrd[j * 3 + 1] - cy;
            dz = scrd[j * 3 + 2] - cz;
            d = sqrtf(dx * dx + dy * dy + dz * dz);
            sp = ssp[j];
        }
        bool inR = valid && (d <= RCR_F);
        bool inA = valid && (d <= RCA_F);

        unsigned mybR = 0, mybA = 0;
        #pragma unroll
        for (int k = 0; k < NS; k++) {
            unsigned bkR = __ballot_sync(FULLM, inR && (sp == k));
            unsigned bkA = __ballot_sync(FULLM, inA && (sp == k));
            if (lane == k) {
                cntRspw[wid][k] = __popc(bkR);
                cntAspw[wid][k] = __popc(bkA);
            }
            if (sp == k) { mybR = bkR; mybA = bkA; }
        }
        int rankR = __popc(mybR & ltm);
        int rankA = __popc(mybA & ltm);
        __syncthreads();

        // per-warp redundant scans of species counts (R and A)
        int totR = 0, ownpreR = 0, totA = 0, ownpreA = 0;
        if (lane < NS) {
            int aR = 0, aA = 0;
            #pragma unroll
            for (int w = 0; w < NWARP; w++) {
                int cR = cntRspw[w][lane];
                int cA = cntAspw[w][lane];
                if (w == wid) { ownpreR = aR; ownpreA = aA; }
                aR += cR; aA += cA;
            }
            totR = aR; totA = aA;
        }
        int scR = totR, scA = totA;
        #pragma unroll
        for (int o = 1; o < 8; o <<= 1) {
            int vR = __shfl_up_sync(FULLM, scR, o);
            int vA = __shfl_up_sync(FULLM, scA, o);
            if (lane >= o) { scR += vR; scA += vA; }
        }
        int startR = scR - totR;          // exclusive, lanes 0..4 meaningful
        int startA = scA - totA;
        if (wid == 0 && lane <= NS) {
            rstart[lane] = startR;        // lane==NS -> total
            astart[lane] = startA;
        }

        // angular species counts per lane (lane<NS): totA; bucket sizes lanes 0..9
        {
            int s1 = (lane < 4) ? 0 : (lane < 7) ? 1 : (lane < 9) ? 2 : 3;
            int row0 = (s1 == 0) ? 0 : (s1 == 1) ? 4 : (s1 == 2) ? 7 : 9;
            int s2 = s1 + (lane - row0);
            int n1 = __shfl_sync(FULLM, totA, s1);
            int n2 = __shfl_sync(FULLM, totA, s2);
            int sz = (lane < NPAIRS_SP) ? ((s1 == s2) ? (n1 * (n1 - 1)) / 2 : n1 * n2) : 0;
            int incl = sz;
            #pragma unroll
            for (int o = 1; o < 16; o <<= 1) {
                int v = __shfl_up_sync(FULLM, incl, o);
                if (lane >= o) incl += v;
            }
            if (wid == 0) {
                if (lane == 0) pbnd[0] = 0;
                if (lane < NPAIRS_SP) pbnd[lane + 1] = incl;
            }
        }

        int radoff = __shfl_sync(FULLM, startR + ownpreR, valid ? sp : 0);
        int angoff = __shfl_sync(FULLM, startA + ownpreA, valid ? sp : 0);
        if (inR) {
            int off = radoff + rankR;
            dR[off] = d;
            qfcR[off] = 0.25f * (0.5f * __cosf(d * (PI_F / RCR_F)) + 0.5f);
        }
        if (inA) {
            int off = angoff + rankA;
            avx[off] = dx; avy[off] = dy; avz[off] = dz;
            ad[off] = d;
            afc[off] = 0.5f * __cosf(d * (PI_F / RCA_F)) + 0.5f;
            arinv[off] = __fdividef(1.0f, fmaxf(d, 1e-8f));
        }
    }
    __syncthreads();   // lists + pbnd + astart visible
    const int npairs = pbnd[NPAIRS_SP];

    // ---- phase 2: angular pairs, analytic bucket enumeration ----
    const int s0 = (tid >> 3) & 3, t0 = tid & 7;
    float acc0 = 0.f, acc1 = 0.f, acc2 = 0.f;

    for (int base = 0; base < npairs; base += CHUNK) {
        if (base > 0) __syncthreads();   // protect previous chunk's scan
        const int cend = min(base + CHUNK, npairs);

        int p = base + tid;
        if (p < npairs) {
            // locate bucket k: 9 compares against pbnd
            int k = 0, pbk = 0;
            #pragma unroll
            for (int jj = 1; jj < NPAIRS_SP; jj++) {
                int t = pbnd[jj];
                if (p >= t) { k = jj; pbk = t; }
            }
            int r = p - pbk;
            int s1 = (k < 4) ? 0 : (k < 7) ? 1 : (k < 9) ? 2 : 3;
            int row0 = (s1 == 0) ? 0 : (s1 == 1) ? 4 : (s1 == 2) ? 7 : 9;
            int s2 = s1 + (k - row0);
            int as1 = astart[s1], as2 = astart[s2];
            int a, b;
            if (s1 == s2) {
                int n = astart[s1 + 1] - as1;
                int ap, bp;
                decode_tri(r, n, ap, bp);
                a = as1 + ap; b = as1 + bp;
            } else {
                int n2c = astart[s2 + 1] - as2;
                int ap = __float2int_rz((float)r * __frcp_rn((float)n2c));
                while (ap * n2c > r) ap--;
                while ((ap + 1) * n2c <= r) ap++;
                a = as1 + ap;
                b = as2 + (r - ap * n2c);
            }
            int slot = p - base;   // storage IS bucket-sorted by construction

            float d1 = ad[a], d2 = ad[b];
            float dot = avx[a] * avx[b] + avy[a] * avy[b] + avz[a] * avz[b];
            float cosv = 0.95f * dot * arinv[a] * arinv[b];
            float sinv = sqrtf(fmaxf(1.0f - cosv * cosv, 0.0f));
            float dm = 0.5f * (d1 + d2);
            float fcj2 = 2.0f * afc[a] * afc[b];

            float2* f1p = (float2*)(f1s + slot * F1STR);
            #pragma unroll
            for (int t = 0; t < NSHFZ; t += 2) {
                float c0 = cosv * cshfz[t] + sinv * sshfz[t];
                float c1 = cosv * cshfz[t + 1] + sinv * sshfz[t + 1];
                float v0 = pow_zeta(0.5f * (1.0f + c0), zeta, z32);
                float v1 = pow_zeta(0.5f * (1.0f + c1), zeta, z32);
                f1p[t >> 1] = make_float2(v0, v1);
            }
            #pragma unroll
            for (int s = 0; s < NSHFA; s++) {
                float dd = dm - shfa[s];
                f2s[slot * 5 + s] = fcj2 * __expf(-etaA * dd * dd);
            }
        }
        __syncthreads();

        // feature accumulation: warp w -> bucket w, then 4+w; warps 0,1 -> 8,9
        {
            int qb = max(pbnd[wid], base) - base;
            int qe = min(pbnd[wid + 1], cend) - base;
            float xa = 0.f, xb = 0.f;
            int q = qb;
            for (; q + 1 < qe; q += 2) {
                xa += f1s[q * F1STR + t0] * f2s[q * 5 + s0];
                xb += f1s[(q + 1) * F1STR + t0] * f2s[(q + 1) * 5 + s0];
            }
            if (q < qe) xa += f1s[q * F1STR + t0] * f2s[q * 5 + s0];
            acc0 += xa + xb;
        }
        {
            int qb = max(pbnd[4 + wid], base) - base;
            int qe = min(pbnd[5 + wid], cend) - base;
            float xa = 0.f, xb = 0.f;
            int q = qb;
            for (; q + 1 < qe; q += 2) {
                xa += f1s[q * F1STR + t0] * f2s[q * 5 + s0];
                xb += f1s[(q + 1) * F1STR + t0] * f2s[(q + 1) * 5 + s0];
            }
            if (q < qe) xa += f1s[q * F1STR + t0] * f2s[q * 5 + s0];
            acc1 += xa + xb;
        }
        if (wid < 2) {
            int qb = max(pbnd[8 + wid], base) - base;
            int qe = min(pbnd[9 + wid], cend) - base;
            float xa = 0.f, xb = 0.f;
            int q = qb;
            for (; q + 1 < qe; q += 2) {
                xa += f1s[q * F1STR + t0] * f2s[q * 5 + s0];
                xb += f1s[(q + 1) * F1STR + t0] * f2s[(q + 1) * 5 + s0];
            }
            if (q < qe) xa += f1s[q * F1STR + t0] * f2s[q * 5 + s0];
            acc2 += xa + xb;
        }
    }

    // ---- phase 3: radial (registers -> gmem) + angular writeout ----
    float* o = out + ((size_t)m * NA + i) * AEV_LEN;
    if (tid < RAD_FEAT) {
        int sp = tid >> 4;
        float sk = shfr[tid & 15];
        float acc = 0.0f;
        int jb = rstart[sp], je = rstart[sp + 1];
        for (int j = jb; j < je; j++) {
            float t = dR[j] - sk;
            acc += qfcR[j] * __expf(-etaR * t * t);
        }
        o[tid] = acc;
    }
    o[RAD_FEAT + tid] = acc0;
    o[RAD_FEAT + 128 + tid] = acc1;
    if (tid < 64) o[RAD_FEAT + 256 + tid] = acc2;
}

extern "C" void kernel_launch(void* const* d_in, const int* in_sizes, int n_in,
                              void* d_out, int out_size) {
    const float* coords = (const float*)d_in[0];
    const float* EtaR   = (const float*)d_in[1];
    const float* ShfR   = (const float*)d_in[2];
    const float* EtaA   = (const float*)d_in[3];
    const float* Zeta   = (const float*)d_in[4];
    const float* ShfA   = (const float*)d_in[5];
    const float* ShfZ   = (const float*)d_in[6];
    const int*   spec   = (const int*)d_in[7];
    float* out = (float*)d_out;

    int MA = in_sizes[7];
    int M = MA / NA;

    dim3 grid(NA, M);
    aev_kernel<<<grid, NTHR>>>(coords, EtaR, ShfR, EtaA, Zeta, ShfA, ShfZ, spec, out);
}

// round 17
// speedup vs baseline: 1.0622x; 1.0622x over previous
#include <cuda_runtime.h>
#include <math.h>

#define NA 48
#define NS 4
#define NSHFR 16
#define NSHFA 4
#define NSHFZ 8
#define RAD_FEAT (NS * NSHFR)                     // 64
#define ANG_SUB (NSHFA * NSHFZ)                   // 32
#define NPAIRS_SP (NS * (NS + 1) / 2)             // 10
#define ANG_FEAT (NPAIRS_SP * ANG_SUB)            // 320
#define AEV_LEN (RAD_FEAT + ANG_FEAT)             // 384
#define RCR_F 5.2f
#define RCA_F 3.5f
#define PI_F 3.14159265358979323846f
#define NTHR 128
#define NWARP 4
#define CHUNK 128
#define QSTR 132                                  // row stride (words) for f1T/f2T
#define FULLM 0xffffffffu

__device__ __forceinline__ float pow_zeta(float x, float zeta, bool z32) {
    if (z32) {
        float y = x * x;  // ^2
        y = y * y;        // ^4
        y = y * y;        // ^8
        y = y * y;        // ^16
        return y * y;     // ^32
    }
    return __powf(x, zeta);
}

// decode triangle pair index r -> (a,b), a<b among n items
__device__ __forceinline__ void decode_tri(int r, int n, int& a, int& b) {
    float fn = (float)n;
    float tt = 2.0f * fn - 1.0f;
    a = (int)(0.5f * (tt - sqrtf(fmaxf(tt * tt - 8.0f * (float)r, 0.0f))));
    while (a > 0 && r < a * n - (a * (a + 1)) / 2) a--;
    while (r >= (a + 1) * n - ((a + 1) * (a + 2)) / 2) a++;
    b = r - (a * n - (a * (a + 1)) / 2) + a + 1;
}

__global__ __launch_bounds__(NTHR, 12)
void aev_kernel(const float* __restrict__ coords,   // (M, A, 3)
                const float* __restrict__ gEtaR,
                const float* __restrict__ gShfR,    // (16,)
                const float* __restrict__ gEtaA,
                const float* __restrict__ gZeta,
                const float* __restrict__ gShfA,    // (4,)
                const float* __restrict__ gShfZ,    // (8,)
                const int*   __restrict__ species,  // (M, A)
                float* __restrict__ out)            // (M, A, 384)
{
    const int i = blockIdx.x;
    const int m = blockIdx.y;
    const int tid = threadIdx.x;
    const int lane = tid & 31;
    const int wid = tid >> 5;
    const unsigned ltm = (1u << lane) - 1u;

    __shared__ float scrd[NA * 3];
    __shared__ int   ssp[NA];
    __shared__ float shfr[NSHFR], shfa[NSHFA];
    __shared__ float cshfz[NSHFZ], sshfz[NSHFZ];
    __shared__ float s_etaR, s_etaA, s_zeta;
    __shared__ float dR[NA], qfcR[NA];
    __shared__ int   cntRspw[NWARP][NS];
    __shared__ int   cntAspw[NWARP][NS];
    __shared__ int   rstart[NS + 1];
    __shared__ int   astart[NS + 1];
    __shared__ int   pbnd[NPAIRS_SP + 1];
    __shared__ float avx[NA], avy[NA], avz[NA], ad[NA], afc[NA], arinv[NA];
    __shared__ float f1T[2][NSHFZ * QSTR];         // [buf][t][q]
    __shared__ float f2T[2][NSHFA * QSTR];         // [buf][s][q]

    // ---- phase 0: load ----
    if (tid < 36)
        ((float4*)scrd)[tid] = ((const float4*)(coords + (size_t)m * NA * 3))[tid];
    if (tid >= 64 && tid < 64 + NA)
        ssp[tid - 64] = species[(size_t)m * NA + (tid - 64)];
    if (tid >= 36 && tid < 52) shfr[tid - 36] = gShfR[tid - 36];
    if (tid >= 52 && tid < 56) shfa[tid - 52] = gShfA[tid - 52];
    if (tid >= 112 && tid < 120) {
        float z = gShfZ[tid - 112];
        cshfz[tid - 112] = cosf(z);
        sshfz[tid - 112] = sinf(z);
    }
    if (tid == 120) s_etaR = gEtaR[0];
    if (tid == 121) s_etaA = gEtaA[0];
    if (tid == 122) s_zeta = gZeta[0];
    __syncthreads();

    const float cx = scrd[i * 3], cy = scrd[i * 3 + 1], cz = scrd[i * 3 + 2];
    const float etaR = s_etaR, etaA = s_etaA, zeta = s_zeta;
    const bool z32 = (zeta == 32.0f);

    // ---- phase 1: compaction; BOTH lists species-sorted ----
    {
        int j = tid;
        bool valid = (j < NA) && (j != i);
        float dx = 0.f, dy = 0.f, dz = 0.f, d = 1e9f;
        int sp = 0;
        if (valid) {
            dx = scrd[j * 3] - cx;
            dy = scrd[j * 3 + 1] - cy;
            dz = scrd[j * 3 + 2] - cz;
            d = sqrtf(dx * dx + dy * dy + dz * dz);
            sp = ssp[j];
        }
        bool inR = valid && (d <= RCR_F);
        bool inA = valid && (d <= RCA_F);

        unsigned mybR = 0, mybA = 0;
        #pragma unroll
        for (int k = 0; k < NS; k++) {
            unsigned bkR = __ballot_sync(FULLM, inR && (sp == k));
            unsigned bkA = __ballot_sync(FULLM, inA && (sp == k));
            if (lane == k) {
                cntRspw[wid][k] = __popc(bkR);
                cntAspw[wid][k] = __popc(bkA);
            }
            if (sp == k) { mybR = bkR; mybA = bkA; }
        }
        int rankR = __popc(mybR & ltm);
        int rankA = __popc(mybA & ltm);
        __syncthreads();

        int totR = 0, ownpreR = 0, totA = 0, ownpreA = 0;
        if (lane < NS) {
            int aR = 0, aA = 0;
            #pragma unroll
            for (int w = 0; w < NWARP; w++) {
                int cR = cntRspw[w][lane];
                int cA = cntAspw[w][lane];
                if (w == wid) { ownpreR = aR; ownpreA = aA; }
                aR += cR; aA += cA;
            }
            totR = aR; totA = aA;
        }
        int scR = totR, scA = totA;
        #pragma unroll
        for (int o = 1; o < 8; o <<= 1) {
            int vR = __shfl_up_sync(FULLM, scR, o);
            int vA = __shfl_up_sync(FULLM, scA, o);
            if (lane >= o) { scR += vR; scA += vA; }
        }
        int startR = scR - totR;
        int startA = scA - totA;
        if (wid == 0 && lane <= NS) {
            rstart[lane] = startR;
            astart[lane] = startA;
        }

        // bucket pair-count bounds (lanes 0..9)
        {
            int s1 = (lane < 4) ? 0 : (lane < 7) ? 1 : (lane < 9) ? 2 : 3;
            int row0 = (s1 == 0) ? 0 : (s1 == 1) ? 4 : (s1 == 2) ? 7 : 9;
            int s2 = s1 + (lane - row0);
            int n1 = __shfl_sync(FULLM, totA, s1);
            int n2 = __shfl_sync(FULLM, totA, s2);
            int sz = (lane < NPAIRS_SP) ? ((s1 == s2) ? (n1 * (n1 - 1)) / 2 : n1 * n2) : 0;
            int incl = sz;
            #pragma unroll
            for (int o = 1; o < 16; o <<= 1) {
                int v = __shfl_up_sync(FULLM, incl, o);
                if (lane >= o) incl += v;
            }
            if (wid == 0) {
                if (lane == 0) pbnd[0] = 0;
                if (lane < NPAIRS_SP) pbnd[lane + 1] = incl;
            }
        }

        int radoff = __shfl_sync(FULLM, startR + ownpreR, valid ? sp : 0);
        int angoff = __shfl_sync(FULLM, startA + ownpreA, valid ? sp : 0);
        if (inR) {
            int off = radoff + rankR;
            dR[off] = d;
            qfcR[off] = 0.25f * (0.5f * __cosf(d * (PI_F / RCR_F)) + 0.5f);
        }
        if (inA) {
            int off = angoff + rankA;
            avx[off] = dx; avy[off] = dy; avz[off] = dz;
            ad[off] = d;
            afc[off] = 0.5f * __cosf(d * (PI_F / RCA_F)) + 0.5f;
            arinv[off] = __fdividef(1.0f, fmaxf(d, 1e-8f));
        }
    }
    __syncthreads();
    const int npairs = pbnd[NPAIRS_SP];

    // ---- phase 2: angular pairs; transposed factors, double buffer, 1 sync/chunk ----
    const int s0 = (tid >> 3) & 3, t0 = tid & 7;
    float acc0 = 0.f, acc1 = 0.f, acc2 = 0.f;

    for (int base = 0; base < npairs; base += CHUNK) {
        const int cend = min(base + CHUNK, npairs);
        const int buf = (base >> 7) & 1;
        float* F1 = f1T[buf];
        float* F2 = f2T[buf];

        int p = base + tid;
        if (p < npairs) {
            // bucket via 9 compares
            int k = 0, pbk = 0;
            #pragma unroll
            for (int jj = 1; jj < NPAIRS_SP; jj++) {
                int t = pbnd[jj];
                if (p >= t) { k = jj; pbk = t; }
            }
            int r = p - pbk;
            int s1 = (k < 4) ? 0 : (k < 7) ? 1 : (k < 9) ? 2 : 3;
            int row0 = (s1 == 0) ? 0 : (s1 == 1) ? 4 : (s1 == 2) ? 7 : 9;
            int s2 = s1 + (k - row0);
            int as1 = astart[s1], as2 = astart[s2];
            int a, b;
            if (s1 == s2) {
                int n = astart[s1 + 1] - as1;
                int ap, bp;
                decode_tri(r, n, ap, bp);
                a = as1 + ap; b = as1 + bp;
            } else {
                int n2c = astart[s2 + 1] - as2;
                int ap = __float2int_rz((float)r * __frcp_rn((float)n2c));
                while (ap * n2c > r) ap--;
                while ((ap + 1) * n2c <= r) ap++;
                a = as1 + ap;
                b = as2 + (r - ap * n2c);
            }

            float d1 = ad[a], d2 = ad[b];
            float dot = avx[a] * avx[b] + avy[a] * avy[b] + avz[a] * avz[b];
            float cosv = 0.95f * dot * arinv[a] * arinv[b];
            float sinv = sqrtf(fmaxf(1.0f - cosv * cosv, 0.0f));
            float dm = 0.5f * (d1 + d2);
            float fcj2 = 2.0f * afc[a] * afc[b];

            // slot == tid (analytic order); transposed stores, conflict-free
            #pragma unroll
            for (int t = 0; t < NSHFZ; t++) {
                float c = cosv * cshfz[t] + sinv * sshfz[t];
                F1[t * QSTR + tid] = pow_zeta(0.5f * (1.0f + c), zeta, z32);
            }
            #pragma unroll
            for (int s = 0; s < NSHFA; s++) {
                float dd = dm - shfa[s];
                F2[s * QSTR + tid] = fcj2 * __expf(-etaA * dd * dd);
            }
        }
        __syncthreads();   // the ONLY barrier per chunk

        // feature scan: float2 over q; rows fixed per lane
        const float* r1 = F1 + t0 * QSTR;
        const float* r2 = F2 + s0 * QSTR;
        #pragma unroll
        for (int pass = 0; pass < 3; pass++) {
            int bk = pass * NWARP + wid;
            if (pass == 2 && wid >= 2) break;
            int qb = max(pbnd[bk], base) - base;
            int qe = min(pbnd[bk + 1], cend) - base;
            if (qb >= qe) continue;
            float xa = 0.f, xb = 0.f;
            int q = qb;
            if (q & 1) { xa += r1[q] * r2[q]; q++; }
            const float2* v1 = (const float2*)(r1 + q);
            const float2* v2 = (const float2*)(r2 + q);
            int nv = (qe - q) >> 1;
            for (int u = 0; u < nv; u++) {
                float2 x = v1[u], y = v2[u];
                xa += x.x * y.x;
                xb += x.y * y.y;
            }
            q += nv * 2;
            if (q < qe) xa += r1[q] * r2[q];
            float sum = xa + xb;
            if (pass == 0) acc0 += sum;
            else if (pass == 1) acc1 += sum;
            else acc2 += sum;
        }
    }

    // ---- phase 3: radial + writeout ----
    float* o = out + ((size_t)m * NA + i) * AEV_LEN;
    if (tid < RAD_FEAT) {
        int sp = tid >> 4;
        float sk = shfr[tid & 15];
        float acc = 0.0f;
        int jb = rstart[sp], je = rstart[sp + 1];
        for (int j = jb; j < je; j++) {
            float t = dR[j] - sk;
            acc += qfcR[j] * __expf(-etaR * t * t);
        }
        o[tid] = acc;
    }
    o[RAD_FEAT + tid] = acc0;
    o[RAD_FEAT + 128 + tid] = acc1;
    if (tid < 64) o[RAD_FEAT + 256 + tid] = acc2;
}

extern "C" void kernel_launch(void* const* d_in, const int* in_sizes, int n_in,
                              void* d_out, int out_size) {
    const float* coords = (const float*)d_in[0];
    const float* EtaR   = (const float*)d_in[1];
    const float* ShfR   = (const float*)d_in[2];
    const float* EtaA   = (const float*)d_in[3];
    const float* Zeta   = (const float*)d_in[4];
    const float* ShfA   = (const float*)d_in[5];
    const float* ShfZ   = (const float*)d_in[6];
    const int*   spec   = (const int*)d_in[7];
    float* out = (float*)d_out;

    int MA = in_sizes[7];
    int M = MA / NA;

    dim3 grid(NA, M);
    aev_kernel<<<grid, NTHR>>>(coords, EtaR, ShfR, EtaA, Zeta, ShfA, ShfZ, spec, out);
}